// round 4
// baseline (speedup 1.0000x reference)
#include <cuda_runtime.h>

#define N_NODES 100000
#define N_EDGES 1600000
#define F 128
#define NCLS 64

// ---------------- scratch (no allocation allowed; __device__ globals) ------
__device__ float g_bufA[(size_t)N_NODES * F];   // agg output (norm-scaled)
__device__ float g_bufB[(size_t)N_NODES * F];   // hidden activations
__device__ int   g_counts[N_NODES];
__device__ int   g_rowstart[N_NODES + 1];
__device__ int   g_cursor[N_NODES];
__device__ int   g_eidx[N_EDGES];
__device__ int   g_blocksums[128];

// ---------------- CSR build -----------------------------------------------
__global__ void k_zero_counts() {
    int i = blockIdx.x * blockDim.x + threadIdx.x;
    if (i < N_NODES) g_counts[i] = 0;
}

__global__ void k_hist(const int* __restrict__ dst) {
    int e = blockIdx.x * blockDim.x + threadIdx.x;
    if (e < N_EDGES) atomicAdd(&g_counts[dst[e]], 1);
}

// block-level Hillis-Steele scan, 1024 elems/block
__global__ void k_scan1() {
    __shared__ int s[1024];
    int t = threadIdx.x;
    int i = blockIdx.x * 1024 + t;
    int v = (i < N_NODES) ? g_counts[i] : 0;
    s[t] = v;
    __syncthreads();
    for (int off = 1; off < 1024; off <<= 1) {
        int x = (t >= off) ? s[t - off] : 0;
        __syncthreads();
        s[t] += x;
        __syncthreads();
    }
    if (i < N_NODES) g_rowstart[i] = s[t] - v;   // exclusive
    if (t == 1023) g_blocksums[blockIdx.x] = s[1023];
}

__global__ void k_scan2(int nblocks) {
    __shared__ int s[128];
    int t = threadIdx.x;
    int v = (t < nblocks) ? g_blocksums[t] : 0;
    s[t] = v;
    __syncthreads();
    for (int off = 1; off < 128; off <<= 1) {
        int x = (t >= off) ? s[t - off] : 0;
        __syncthreads();
        s[t] += x;
        __syncthreads();
    }
    if (t < nblocks) g_blocksums[t] = s[t] - v;  // exclusive
}

__global__ void k_scan3() {
    int i = blockIdx.x * blockDim.x + threadIdx.x;
    if (i < N_NODES) {
        int r = g_rowstart[i] + g_blocksums[i >> 10];
        g_rowstart[i] = r;
        g_cursor[i]   = r;
    }
    if (i == N_NODES) g_rowstart[N_NODES] = N_EDGES;
}

__global__ void k_scatter(const int* __restrict__ src, const int* __restrict__ dst) {
    int e = blockIdx.x * blockDim.x + threadIdx.x;
    if (e < N_EDGES) {
        int p = atomicAdd(&g_cursor[dst[e]], 1);
        g_eidx[p] = src[e];
    }
}

// ---------------- aggregation: warp per node, lane = float4 chunk ---------
// out[node] = norm[node] * sum_{e in in(node)} h[src(e)]
__global__ void k_agg(const float* __restrict__ h, const float* __restrict__ norm,
                      float* __restrict__ out) {
    int w = (blockIdx.x * blockDim.x + threadIdx.x) >> 5;
    int lane = threadIdx.x & 31;
    if (w >= N_NODES) return;
    int beg = g_rowstart[w];
    int end = g_rowstart[w + 1];

    float ax = 0.f, ay = 0.f, az = 0.f, aw = 0.f;
    int e = beg;
    // 4-way unroll for MLP (independent L2 gathers in flight)
    for (; e + 4 <= end; e += 4) {
        int s0 = g_eidx[e + 0];
        int s1 = g_eidx[e + 1];
        int s2 = g_eidx[e + 2];
        int s3 = g_eidx[e + 3];
        float4 v0 = *(const float4*)(h + (size_t)s0 * F + lane * 4);
        float4 v1 = *(const float4*)(h + (size_t)s1 * F + lane * 4);
        float4 v2 = *(const float4*)(h + (size_t)s2 * F + lane * 4);
        float4 v3 = *(const float4*)(h + (size_t)s3 * F + lane * 4);
        ax += v0.x + v1.x + v2.x + v3.x;
        ay += v0.y + v1.y + v2.y + v3.y;
        az += v0.z + v1.z + v2.z + v3.z;
        aw += v0.w + v1.w + v2.w + v3.w;
    }
    for (; e < end; ++e) {
        int s = g_eidx[e];
        float4 v = *(const float4*)(h + (size_t)s * F + lane * 4);
        ax += v.x; ay += v.y; az += v.z; aw += v.w;
    }
    float nf = norm[w];
    float4 r = make_float4(ax * nf, ay * nf, az * nf, aw * nf);
    *(float4*)(out + (size_t)w * F + lane * 4) = r;
}

// ---------------- GEMM: C[M,NOUT] = A[M,128] @ W[128,NOUT] + b (opt relu) --
// Tile: 128 rows/block, full K=128, full NOUT. 256 threads, 8xTN per thread.
template<int NOUT, bool RELU>
__global__ void k_gemm(const float* __restrict__ A, const float* __restrict__ W,
                       const float* __restrict__ bias, float* __restrict__ C) {
    constexpr int TN = NOUT / 16;          // 8 for 128, 4 for 64
    extern __shared__ float smem[];
    float* As = smem;                      // [128][132] padded
    float* Ws = smem + 128 * 132;          // [128][NOUT]

    int tid = threadIdx.x;                 // 256 threads
    int m0 = blockIdx.x * 128;

    // load W tile (whole W)
    for (int i = tid * 4; i < 128 * NOUT; i += 256 * 4)
        *(float4*)&Ws[i] = *(const float4*)&W[i];

    // load A tile (row-major, pad stride 132)
    for (int idx = tid; idx < 128 * 32; idx += 256) {
        int m = idx >> 5, kq = idx & 31;
        float4 v = make_float4(0.f, 0.f, 0.f, 0.f);
        if (m0 + m < N_NODES)
            v = *(const float4*)&A[(size_t)(m0 + m) * 128 + kq * 4];
        *(float4*)&As[m * 132 + kq * 4] = v;
    }
    __syncthreads();

    int ty = tid >> 4, tx = tid & 15;      // 16x16 thread grid
    int rm = ty * 8;
    int cn = tx * TN;

    float acc[8][TN];
#pragma unroll
    for (int r = 0; r < 8; ++r)
#pragma unroll
        for (int c = 0; c < TN; ++c) acc[r][c] = 0.f;

#pragma unroll 4
    for (int k = 0; k < 128; ++k) {
        float a[8];
#pragma unroll
        for (int r = 0; r < 8; ++r) a[r] = As[(rm + r) * 132 + k];
        float w[TN];
#pragma unroll
        for (int c = 0; c < TN; c += 4)
            *(float4*)&w[c] = *(float4*)&Ws[k * NOUT + cn + c];
#pragma unroll
        for (int r = 0; r < 8; ++r)
#pragma unroll
            for (int c = 0; c < TN; ++c)
                acc[r][c] = fmaf(a[r], w[c], acc[r][c]);
    }

    float bv[TN];
#pragma unroll
    for (int c = 0; c < TN; c += 4)
        *(float4*)&bv[c] = *(const float4*)&bias[cn + c];

#pragma unroll
    for (int r = 0; r < 8; ++r) {
        int m = m0 + rm + r;
        if (m < N_NODES) {
#pragma unroll
            for (int c = 0; c < TN; ++c) {
                float o = acc[r][c] + bv[c];
                if (RELU) o = fmaxf(o, 0.f);
                acc[r][c] = o;
            }
#pragma unroll
            for (int c = 0; c < TN; c += 4)
                *(float4*)&C[(size_t)m * NOUT + cn + c] = *(float4*)&acc[r][c];
        }
    }
}

// ---------------- launch ---------------------------------------------------
extern "C" void kernel_launch(void* const* d_in, const int* in_sizes, int n_in,
                              void* d_out, int out_size) {
    const float* features = (const float*)d_in[0];
    const float* norm     = (const float*)d_in[1];
    const float* W0       = (const float*)d_in[2];
    const float* b0       = (const float*)d_in[3];
    const float* W1       = (const float*)d_in[4];
    const float* b1       = (const float*)d_in[5];
    const float* W2       = (const float*)d_in[6];
    const float* b2       = (const float*)d_in[7];
    const int*   src      = (const int*)d_in[8];
    const int*   dst      = (const int*)d_in[9];
    float* out = (float*)d_out;

    float *bufA = nullptr, *bufB = nullptr;
    cudaGetSymbolAddress((void**)&bufA, g_bufA);
    cudaGetSymbolAddress((void**)&bufB, g_bufB);

    const int SM128 = 128 * 132 * 4 + 128 * 128 * 4;  // 133120 B
    const int SM64  = 128 * 132 * 4 + 128 * 64  * 4;  // 100352 B
    cudaFuncSetAttribute(k_gemm<128, true>,  cudaFuncAttributeMaxDynamicSharedMemorySize, SM128);
    cudaFuncSetAttribute(k_gemm<64,  false>, cudaFuncAttributeMaxDynamicSharedMemorySize, SM64);

    // CSR build (by dst)
    k_zero_counts<<<(N_NODES + 255) / 256, 256>>>();
    k_hist<<<(N_EDGES + 255) / 256, 256>>>(dst);
    int nb = (N_NODES + 1023) / 1024;   // 98
    k_scan1<<<nb, 1024>>>();
    k_scan2<<<1, 128>>>(nb);
    k_scan3<<<(N_NODES + 1 + 255) / 256, 256>>>();
    k_scatter<<<(N_EDGES + 255) / 256, 256>>>(src, dst);

    dim3 aggGrid((N_NODES + 7) / 8);    // 8 warps/block of 256 threads
    int gemmGrid = (N_NODES + 127) / 128;

    // layer 0
    k_agg<<<aggGrid, 256>>>(features, norm, bufA);
    k_gemm<128, true><<<gemmGrid, 256, SM128>>>(bufA, W0, b0, bufB);
    // layer 1
    k_agg<<<aggGrid, 256>>>(bufB, norm, bufA);
    k_gemm<128, true><<<gemmGrid, 256, SM128>>>(bufA, W1, b1, bufB);
    // layer 2 (no relu, 64 classes, write straight to d_out)
    k_agg<<<aggGrid, 256>>>(bufB, norm, bufA);
    k_gemm<64, false><<<gemmGrid, 256, SM64>>>(bufA, W2, b2, out);
}

// round 5
// speedup vs baseline: 1.5936x; 1.5936x over previous
#include <cuda_runtime.h>
#include <cstdint>

#define N_NODES 100000
#define N_EDGES 1600000
#define F 128
#define NCLS 64

// ---------------- scratch (no allocation allowed; __device__ globals) ------
__device__ float g_bufA[(size_t)N_NODES * F];   // agg output (norm-scaled)
__device__ float g_bufB[(size_t)N_NODES * F];   // hidden activations
__device__ int   g_counts[N_NODES];
__device__ int   g_rowstart[N_NODES + 1];
__device__ int   g_cursor[N_NODES];
__device__ int   g_eidx[N_EDGES];
__device__ int   g_blocksums[128];

// ---------------- CSR build -----------------------------------------------
__global__ void k_zero_counts() {
    int i = blockIdx.x * blockDim.x + threadIdx.x;
    if (i < N_NODES) g_counts[i] = 0;
}

__global__ void k_hist(const int* __restrict__ dst) {
    int e = blockIdx.x * blockDim.x + threadIdx.x;
    if (e < N_EDGES) atomicAdd(&g_counts[dst[e]], 1);
}

// block-level Hillis-Steele scan, 1024 elems/block
__global__ void k_scan1() {
    __shared__ int s[1024];
    int t = threadIdx.x;
    int i = blockIdx.x * 1024 + t;
    int v = (i < N_NODES) ? g_counts[i] : 0;
    s[t] = v;
    __syncthreads();
    for (int off = 1; off < 1024; off <<= 1) {
        int x = (t >= off) ? s[t - off] : 0;
        __syncthreads();
        s[t] += x;
        __syncthreads();
    }
    if (i < N_NODES) g_rowstart[i] = s[t] - v;   // exclusive
    if (t == 1023) g_blocksums[blockIdx.x] = s[1023];
}

__global__ void k_scan2(int nblocks) {
    __shared__ int s[128];
    int t = threadIdx.x;
    int v = (t < nblocks) ? g_blocksums[t] : 0;
    s[t] = v;
    __syncthreads();
    for (int off = 1; off < 128; off <<= 1) {
        int x = (t >= off) ? s[t - off] : 0;
        __syncthreads();
        s[t] += x;
        __syncthreads();
    }
    if (t < nblocks) g_blocksums[t] = s[t] - v;  // exclusive
}

__global__ void k_scan3() {
    int i = blockIdx.x * blockDim.x + threadIdx.x;
    if (i < N_NODES) {
        int r = g_rowstart[i] + g_blocksums[i >> 10];
        g_rowstart[i] = r;
        g_cursor[i]   = r;
    }
    if (i == N_NODES) g_rowstart[N_NODES] = N_EDGES;
}

__global__ void k_scatter(const int* __restrict__ src, const int* __restrict__ dst) {
    int e = blockIdx.x * blockDim.x + threadIdx.x;
    if (e < N_EDGES) {
        int p = atomicAdd(&g_cursor[dst[e]], 1);
        g_eidx[p] = src[e];
    }
}

// ---------------- aggregation: warp per node, lane = float4 chunk ---------
// out[node] = norm[node] * sum_{e in in(node)} h[src(e)]
__global__ void k_agg(const float* __restrict__ h, const float* __restrict__ norm,
                      float* __restrict__ out) {
    int w = (blockIdx.x * blockDim.x + threadIdx.x) >> 5;
    int lane = threadIdx.x & 31;
    if (w >= N_NODES) return;
    int beg = g_rowstart[w];
    int end = g_rowstart[w + 1];

    float ax = 0.f, ay = 0.f, az = 0.f, aw = 0.f;
    int e = beg;
    for (; e + 4 <= end; e += 4) {
        int s0 = g_eidx[e + 0];
        int s1 = g_eidx[e + 1];
        int s2 = g_eidx[e + 2];
        int s3 = g_eidx[e + 3];
        float4 v0 = *(const float4*)(h + (size_t)s0 * F + lane * 4);
        float4 v1 = *(const float4*)(h + (size_t)s1 * F + lane * 4);
        float4 v2 = *(const float4*)(h + (size_t)s2 * F + lane * 4);
        float4 v3 = *(const float4*)(h + (size_t)s3 * F + lane * 4);
        ax += v0.x + v1.x + v2.x + v3.x;
        ay += v0.y + v1.y + v2.y + v3.y;
        az += v0.z + v1.z + v2.z + v3.z;
        aw += v0.w + v1.w + v2.w + v3.w;
    }
    for (; e < end; ++e) {
        int s = g_eidx[e];
        float4 v = *(const float4*)(h + (size_t)s * F + lane * 4);
        ax += v.x; ay += v.y; az += v.z; aw += v.w;
    }
    float nf = norm[w];
    float4 r = make_float4(ax * nf, ay * nf, az * nf, aw * nf);
    *(float4*)(out + (size_t)w * F + lane * 4) = r;
}

// ---------------- tensor-core GEMM (tf32 mma.sync, fp32 accumulate) -------
// C[M, NOUT] = A[M,128] @ W[128,NOUT] + b  (optional relu)
// BLOCK_M = 256 rows, 512 threads (16 warps). Warp grid 4(m) x 4(n):
// each warp computes 64 x (NOUT/4): m-tiles of 16, n-tiles of 8.

__device__ __forceinline__ uint32_t f2tf32(float f) {
    uint32_t u;
    asm("cvt.rna.tf32.f32 %0, %1;" : "=r"(u) : "f"(f));
    return u;
}

__device__ __forceinline__ void mma_tf32(float c[4],
                                         uint32_t a0, uint32_t a1, uint32_t a2, uint32_t a3,
                                         uint32_t b0, uint32_t b1) {
    asm volatile(
        "mma.sync.aligned.m16n8k8.row.col.f32.tf32.tf32.f32 "
        "{%0,%1,%2,%3}, {%4,%5,%6,%7}, {%8,%9}, {%0,%1,%2,%3};\n"
        : "+f"(c[0]), "+f"(c[1]), "+f"(c[2]), "+f"(c[3])
        : "r"(a0), "r"(a1), "r"(a2), "r"(a3), "r"(b0), "r"(b1));
}

template<int NOUT, bool RELU>
__global__ void __launch_bounds__(512, 1)
k_gemm_tc(const float* __restrict__ A, const float* __restrict__ W,
          const float* __restrict__ bias, float* __restrict__ C) {
    constexpr int BM  = 256;
    constexpr int AST = 132;            // A smem stride (words): banks 4r+c, conflict-free
    constexpr int WST = 136;            // W smem stride (words): banks 8c+r, conflict-free
    constexpr int NTILES = NOUT / 32;   // n-tiles per warp (4 for 128, 2 for 64)

    extern __shared__ uint32_t sm[];
    uint32_t* As = sm;                  // [BM][AST] tf32 bits
    uint32_t* Ws = sm + BM * AST;       // [128][WST] tf32 bits

    int tid = threadIdx.x;
    int m0 = blockIdx.x * BM;

    // --- load W [128][NOUT] row-major -> Ws[k][n] as tf32 ---
    for (int idx = tid * 4; idx < 128 * NOUT; idx += 512 * 4) {
        int k = idx / NOUT, n = idx % NOUT;   // n % 4 == 0
        float4 v = *(const float4*)&W[idx];
        uint32_t* p = &Ws[k * WST + n];
        p[0] = f2tf32(v.x); p[1] = f2tf32(v.y);
        p[2] = f2tf32(v.z); p[3] = f2tf32(v.w);
    }

    // --- load A tile [BM][128] -> As as tf32 (zero-pad OOB rows) ---
    for (int idx = tid; idx < BM * 32; idx += 512) {
        int m = idx >> 5, kq = idx & 31;
        float4 v = make_float4(0.f, 0.f, 0.f, 0.f);
        if (m0 + m < N_NODES)
            v = *(const float4*)&A[(size_t)(m0 + m) * 128 + kq * 4];
        uint32_t* p = &As[m * AST + kq * 4];
        p[0] = f2tf32(v.x); p[1] = f2tf32(v.y);
        p[2] = f2tf32(v.z); p[3] = f2tf32(v.w);
    }
    __syncthreads();

    int wid  = tid >> 5, lane = tid & 31;
    int wm   = wid & 3;                 // 0..3 -> 64 rows each
    int wn   = wid >> 2;                // 0..3 -> NOUT/4 cols each
    int mbase = wm * 64;
    int nbase = wn * (NOUT / 4);
    int r = lane >> 2;                  // 0..7
    int c = lane & 3;                   // 0..3

    float acc[4][NTILES][4];
#pragma unroll
    for (int mt = 0; mt < 4; ++mt)
#pragma unroll
        for (int nt = 0; nt < NTILES; ++nt)
#pragma unroll
            for (int i = 0; i < 4; ++i) acc[mt][nt][i] = 0.f;

#pragma unroll 2
    for (int k0 = 0; k0 < 128; k0 += 8) {
        uint32_t af[4][4];
#pragma unroll
        for (int mt = 0; mt < 4; ++mt) {
            int row = mbase + mt * 16 + r;
            af[mt][0] = As[row * AST + k0 + c];
            af[mt][1] = As[(row + 8) * AST + k0 + c];
            af[mt][2] = As[row * AST + k0 + c + 4];
            af[mt][3] = As[(row + 8) * AST + k0 + c + 4];
        }
        uint32_t bf[NTILES][2];
#pragma unroll
        for (int nt = 0; nt < NTILES; ++nt) {
            int col = nbase + nt * 8 + r;
            bf[nt][0] = Ws[(k0 + c) * WST + col];
            bf[nt][1] = Ws[(k0 + c + 4) * WST + col];
        }
#pragma unroll
        for (int mt = 0; mt < 4; ++mt)
#pragma unroll
            for (int nt = 0; nt < NTILES; ++nt)
                mma_tf32(acc[mt][nt], af[mt][0], af[mt][1], af[mt][2], af[mt][3],
                         bf[nt][0], bf[nt][1]);
    }

    // --- epilogue: bias (+relu), write C ---
#pragma unroll
    for (int nt = 0; nt < NTILES; ++nt) {
        int col = nbase + nt * 8 + 2 * c;
        float b0 = bias[col], b1 = bias[col + 1];
#pragma unroll
        for (int mt = 0; mt < 4; ++mt) {
            int row = m0 + mbase + mt * 16 + r;
            float v0 = acc[mt][nt][0] + b0;
            float v1 = acc[mt][nt][1] + b1;
            float v2 = acc[mt][nt][2] + b0;
            float v3 = acc[mt][nt][3] + b1;
            if (RELU) {
                v0 = fmaxf(v0, 0.f); v1 = fmaxf(v1, 0.f);
                v2 = fmaxf(v2, 0.f); v3 = fmaxf(v3, 0.f);
            }
            if (row < N_NODES)
                *(float2*)&C[(size_t)row * NOUT + col] = make_float2(v0, v1);
            if (row + 8 < N_NODES)
                *(float2*)&C[(size_t)(row + 8) * NOUT + col] = make_float2(v2, v3);
        }
    }
}

// ---------------- launch ---------------------------------------------------
extern "C" void kernel_launch(void* const* d_in, const int* in_sizes, int n_in,
                              void* d_out, int out_size) {
    const float* features = (const float*)d_in[0];
    const float* norm     = (const float*)d_in[1];
    const float* W0       = (const float*)d_in[2];
    const float* b0       = (const float*)d_in[3];
    const float* W1       = (const float*)d_in[4];
    const float* b1       = (const float*)d_in[5];
    const float* W2       = (const float*)d_in[6];
    const float* b2       = (const float*)d_in[7];
    const int*   src      = (const int*)d_in[8];
    const int*   dst      = (const int*)d_in[9];
    float* out = (float*)d_out;

    float *bufA = nullptr, *bufB = nullptr;
    cudaGetSymbolAddress((void**)&bufA, g_bufA);
    cudaGetSymbolAddress((void**)&bufB, g_bufB);

    const int SM_GEMM = (256 * 132 + 128 * 136) * 4;   // 204800 B
    cudaFuncSetAttribute(k_gemm_tc<128, true>,  cudaFuncAttributeMaxDynamicSharedMemorySize, SM_GEMM);
    cudaFuncSetAttribute(k_gemm_tc<64,  false>, cudaFuncAttributeMaxDynamicSharedMemorySize, SM_GEMM);

    // CSR build (by dst)
    k_zero_counts<<<(N_NODES + 255) / 256, 256>>>();
    k_hist<<<(N_EDGES + 255) / 256, 256>>>(dst);
    int nb = (N_NODES + 1023) / 1024;   // 98
    k_scan1<<<nb, 1024>>>();
    k_scan2<<<1, 128>>>(nb);
    k_scan3<<<(N_NODES + 1 + 255) / 256, 256>>>();
    k_scatter<<<(N_EDGES + 255) / 256, 256>>>(src, dst);

    dim3 aggGrid((N_NODES + 7) / 8);            // 8 warps/block of 256 threads
    int gemmGrid = (N_NODES + 255) / 256;       // 391

    // layer 0
    k_agg<<<aggGrid, 256>>>(features, norm, bufA);
    k_gemm_tc<128, true><<<gemmGrid, 512, SM_GEMM>>>(bufA, W0, b0, bufB);
    // layer 1
    k_agg<<<aggGrid, 256>>>(bufB, norm, bufA);
    k_gemm_tc<128, true><<<gemmGrid, 512, SM_GEMM>>>(bufA, W1, b1, bufB);
    // layer 2 (no relu, 64 classes, straight to d_out)
    k_agg<<<aggGrid, 256>>>(bufB, norm, bufA);
    k_gemm_tc<64, false><<<gemmGrid, 512, SM_GEMM>>>(bufA, W2, b2, out);
}

// round 6
// speedup vs baseline: 1.7097x; 1.0729x over previous
#include <cuda_runtime.h>
#include <cstdint>

#define N_NODES 100000
#define N_EDGES 1600000
#define F 128
#define NCLS 64

// ---------------- scratch (no allocation allowed; __device__ globals) ------
__device__ float g_bufA[(size_t)N_NODES * F];   // agg output / Y2
__device__ float g_bufB[(size_t)N_NODES * F];   // hidden activations
__device__ int   g_counts[N_NODES];
__device__ int   g_rowstart[N_NODES + 1];
__device__ int   g_cursor[N_NODES];
__device__ int   g_eidx[N_EDGES];
__device__ int   g_blocksums[128];

// ---------------- CSR build -----------------------------------------------
__global__ void k_hist(const int* __restrict__ dst) {
    int e = blockIdx.x * blockDim.x + threadIdx.x;
    if (e < N_EDGES) atomicAdd(&g_counts[dst[e]], 1);
}

// block-level Hillis-Steele scan, 1024 elems/block
__global__ void k_scan1() {
    __shared__ int s[1024];
    int t = threadIdx.x;
    int i = blockIdx.x * 1024 + t;
    int v = (i < N_NODES) ? g_counts[i] : 0;
    s[t] = v;
    __syncthreads();
    for (int off = 1; off < 1024; off <<= 1) {
        int x = (t >= off) ? s[t - off] : 0;
        __syncthreads();
        s[t] += x;
        __syncthreads();
    }
    if (i < N_NODES) g_rowstart[i] = s[t] - v;   // exclusive
    if (t == 1023) g_blocksums[blockIdx.x] = s[1023];
}

__global__ void k_scan2(int nblocks) {
    __shared__ int s[128];
    int t = threadIdx.x;
    int v = (t < nblocks) ? g_blocksums[t] : 0;
    s[t] = v;
    __syncthreads();
    for (int off = 1; off < 128; off <<= 1) {
        int x = (t >= off) ? s[t - off] : 0;
        __syncthreads();
        s[t] += x;
        __syncthreads();
    }
    if (t < nblocks) g_blocksums[t] = s[t] - v;  // exclusive
}

__global__ void k_scan3() {
    int i = blockIdx.x * blockDim.x + threadIdx.x;
    if (i < N_NODES) {
        int r = g_rowstart[i] + g_blocksums[i >> 10];
        g_rowstart[i] = r;
        g_cursor[i]   = r;
    }
    if (i == N_NODES) g_rowstart[N_NODES] = N_EDGES;
}

__global__ void k_scatter(const int* __restrict__ src, const int* __restrict__ dst) {
    int e = blockIdx.x * blockDim.x + threadIdx.x;
    if (e < N_EDGES) {
        int p = atomicAdd(&g_cursor[dst[e]], 1);
        g_eidx[p] = src[e];
    }
}

// ---------------- aggregation (128-wide): warp per node, lane = float4 ----
// out[node] = norm[node] * sum_{e in in(node)} h[src(e)]
__global__ void k_agg(const float* __restrict__ h, const float* __restrict__ norm,
                      float* __restrict__ out) {
    int w = (blockIdx.x * blockDim.x + threadIdx.x) >> 5;
    int lane = threadIdx.x & 31;
    if (w >= N_NODES) return;
    int beg = g_rowstart[w];
    int end = g_rowstart[w + 1];

    float ax = 0.f, ay = 0.f, az = 0.f, aw = 0.f;
    int e = beg;
    for (; e + 4 <= end; e += 4) {
        int s0 = g_eidx[e + 0];
        int s1 = g_eidx[e + 1];
        int s2 = g_eidx[e + 2];
        int s3 = g_eidx[e + 3];
        float4 v0 = *(const float4*)(h + (size_t)s0 * F + lane * 4);
        float4 v1 = *(const float4*)(h + (size_t)s1 * F + lane * 4);
        float4 v2 = *(const float4*)(h + (size_t)s2 * F + lane * 4);
        float4 v3 = *(const float4*)(h + (size_t)s3 * F + lane * 4);
        ax += v0.x + v1.x + v2.x + v3.x;
        ay += v0.y + v1.y + v2.y + v3.y;
        az += v0.z + v1.z + v2.z + v3.z;
        aw += v0.w + v1.w + v2.w + v3.w;
    }
    for (; e < end; ++e) {
        int s = g_eidx[e];
        float4 v = *(const float4*)(h + (size_t)s * F + lane * 4);
        ax += v.x; ay += v.y; az += v.z; aw += v.w;
    }
    float nf = norm[w];
    float4 r = make_float4(ax * nf, ay * nf, az * nf, aw * nf);
    *(float4*)(out + (size_t)w * F + lane * 4) = r;
}

// ---------------- aggregation (64-wide) + norm + bias, final layer --------
// out[node] = norm[node] * sum_{e in in(node)} Y[src(e)] + bias
__global__ void k_agg64_bias(const float* __restrict__ Y, const float* __restrict__ norm,
                             const float* __restrict__ bias, float* __restrict__ out) {
    int w = (blockIdx.x * blockDim.x + threadIdx.x) >> 5;
    int lane = threadIdx.x & 31;
    if (w >= N_NODES) return;
    int beg = g_rowstart[w];
    int end = g_rowstart[w + 1];

    float ax = 0.f, ay = 0.f;
    int e = beg;
    for (; e + 4 <= end; e += 4) {
        int s0 = g_eidx[e + 0];
        int s1 = g_eidx[e + 1];
        int s2 = g_eidx[e + 2];
        int s3 = g_eidx[e + 3];
        float2 v0 = *(const float2*)(Y + (size_t)s0 * NCLS + lane * 2);
        float2 v1 = *(const float2*)(Y + (size_t)s1 * NCLS + lane * 2);
        float2 v2 = *(const float2*)(Y + (size_t)s2 * NCLS + lane * 2);
        float2 v3 = *(const float2*)(Y + (size_t)s3 * NCLS + lane * 2);
        ax += v0.x + v1.x + v2.x + v3.x;
        ay += v0.y + v1.y + v2.y + v3.y;
    }
    for (; e < end; ++e) {
        int s = g_eidx[e];
        float2 v = *(const float2*)(Y + (size_t)s * NCLS + lane * 2);
        ax += v.x; ay += v.y;
    }
    float nf = norm[w];
    float2 b = *(const float2*)(bias + lane * 2);
    float2 r = make_float2(ax * nf + b.x, ay * nf + b.y);
    *(float2*)(out + (size_t)w * NCLS + lane * 2) = r;
}

// ---------------- tensor-core GEMM (tf32 mma.sync, fp32 accumulate) -------
// C[M, NOUT] = A[M,128] @ W[128,NOUT] (+ bias if HASBIAS) (+ relu)
// BLOCK_M = 256 rows, 512 threads (16 warps). Warp grid 4(m) x 4(n).

__device__ __forceinline__ uint32_t f2tf32(float f) {
    uint32_t u;
    asm("cvt.rna.tf32.f32 %0, %1;" : "=r"(u) : "f"(f));
    return u;
}

__device__ __forceinline__ void mma_tf32(float c[4],
                                         uint32_t a0, uint32_t a1, uint32_t a2, uint32_t a3,
                                         uint32_t b0, uint32_t b1) {
    asm volatile(
        "mma.sync.aligned.m16n8k8.row.col.f32.tf32.tf32.f32 "
        "{%0,%1,%2,%3}, {%4,%5,%6,%7}, {%8,%9}, {%0,%1,%2,%3};\n"
        : "+f"(c[0]), "+f"(c[1]), "+f"(c[2]), "+f"(c[3])
        : "r"(a0), "r"(a1), "r"(a2), "r"(a3), "r"(b0), "r"(b1));
}

template<int NOUT, bool RELU, bool HASBIAS>
__global__ void __launch_bounds__(512, 1)
k_gemm_tc(const float* __restrict__ A, const float* __restrict__ W,
          const float* __restrict__ bias, float* __restrict__ C) {
    constexpr int BM  = 256;
    constexpr int AST = 132;            // A smem stride (words): conflict-free
    constexpr int WST = 136;            // W smem stride (words): conflict-free
    constexpr int NTILES = NOUT / 32;   // 4 for 128, 2 for 64

    extern __shared__ uint32_t sm[];
    uint32_t* As = sm;                  // [BM][AST] tf32 bits
    uint32_t* Ws = sm + BM * AST;       // [128][WST] tf32 bits

    int tid = threadIdx.x;
    int m0 = blockIdx.x * BM;

    // load W [128][NOUT] -> Ws[k][n] as tf32
    for (int idx = tid * 4; idx < 128 * NOUT; idx += 512 * 4) {
        int k = idx / NOUT, n = idx % NOUT;
        float4 v = *(const float4*)&W[idx];
        uint32_t* p = &Ws[k * WST + n];
        p[0] = f2tf32(v.x); p[1] = f2tf32(v.y);
        p[2] = f2tf32(v.z); p[3] = f2tf32(v.w);
    }

    // load A tile [BM][128] -> As as tf32 (zero-pad OOB rows)
    for (int idx = tid; idx < BM * 32; idx += 512) {
        int m = idx >> 5, kq = idx & 31;
        float4 v = make_float4(0.f, 0.f, 0.f, 0.f);
        if (m0 + m < N_NODES)
            v = *(const float4*)&A[(size_t)(m0 + m) * 128 + kq * 4];
        uint32_t* p = &As[m * AST + kq * 4];
        p[0] = f2tf32(v.x); p[1] = f2tf32(v.y);
        p[2] = f2tf32(v.z); p[3] = f2tf32(v.w);
    }
    __syncthreads();

    int wid  = tid >> 5, lane = tid & 31;
    int wm   = wid & 3;
    int wn   = wid >> 2;
    int mbase = wm * 64;
    int nbase = wn * (NOUT / 4);
    int r = lane >> 2;
    int c = lane & 3;

    float acc[4][NTILES][4];
#pragma unroll
    for (int mt = 0; mt < 4; ++mt)
#pragma unroll
        for (int nt = 0; nt < NTILES; ++nt)
#pragma unroll
            for (int i = 0; i < 4; ++i) acc[mt][nt][i] = 0.f;

#pragma unroll 2
    for (int k0 = 0; k0 < 128; k0 += 8) {
        uint32_t af[4][4];
#pragma unroll
        for (int mt = 0; mt < 4; ++mt) {
            int row = mbase + mt * 16 + r;
            af[mt][0] = As[row * AST + k0 + c];
            af[mt][1] = As[(row + 8) * AST + k0 + c];
            af[mt][2] = As[row * AST + k0 + c + 4];
            af[mt][3] = As[(row + 8) * AST + k0 + c + 4];
        }
        uint32_t bf[NTILES][2];
#pragma unroll
        for (int nt = 0; nt < NTILES; ++nt) {
            int col = nbase + nt * 8 + r;
            bf[nt][0] = Ws[(k0 + c) * WST + col];
            bf[nt][1] = Ws[(k0 + c + 4) * WST + col];
        }
#pragma unroll
        for (int mt = 0; mt < 4; ++mt)
#pragma unroll
            for (int nt = 0; nt < NTILES; ++nt)
                mma_tf32(acc[mt][nt], af[mt][0], af[mt][1], af[mt][2], af[mt][3],
                         bf[nt][0], bf[nt][1]);
    }

    // epilogue: optional bias (+relu), write C
#pragma unroll
    for (int nt = 0; nt < NTILES; ++nt) {
        int col = nbase + nt * 8 + 2 * c;
        float b0 = 0.f, b1 = 0.f;
        if (HASBIAS) { b0 = bias[col]; b1 = bias[col + 1]; }
#pragma unroll
        for (int mt = 0; mt < 4; ++mt) {
            int row = m0 + mbase + mt * 16 + r;
            float v0 = acc[mt][nt][0] + b0;
            float v1 = acc[mt][nt][1] + b1;
            float v2 = acc[mt][nt][2] + b0;
            float v3 = acc[mt][nt][3] + b1;
            if (RELU) {
                v0 = fmaxf(v0, 0.f); v1 = fmaxf(v1, 0.f);
                v2 = fmaxf(v2, 0.f); v3 = fmaxf(v3, 0.f);
            }
            if (row < N_NODES)
                *(float2*)&C[(size_t)row * NOUT + col] = make_float2(v0, v1);
            if (row + 8 < N_NODES)
                *(float2*)&C[(size_t)(row + 8) * NOUT + col] = make_float2(v2, v3);
        }
    }
}

// ---------------- launch ---------------------------------------------------
extern "C" void kernel_launch(void* const* d_in, const int* in_sizes, int n_in,
                              void* d_out, int out_size) {
    const float* features = (const float*)d_in[0];
    const float* norm     = (const float*)d_in[1];
    const float* W0       = (const float*)d_in[2];
    const float* b0       = (const float*)d_in[3];
    const float* W1       = (const float*)d_in[4];
    const float* b1       = (const float*)d_in[5];
    const float* W2       = (const float*)d_in[6];
    const float* b2       = (const float*)d_in[7];
    const int*   src      = (const int*)d_in[8];
    const int*   dst      = (const int*)d_in[9];
    float* out = (float*)d_out;

    float *bufA = nullptr, *bufB = nullptr;
    int* countsPtr = nullptr;
    cudaGetSymbolAddress((void**)&bufA, g_bufA);
    cudaGetSymbolAddress((void**)&bufB, g_bufB);
    cudaGetSymbolAddress((void**)&countsPtr, g_counts);

    const int SM_GEMM = (256 * 132 + 128 * 136) * 4;   // 204800 B
    cudaFuncSetAttribute(k_gemm_tc<128, true,  true >, cudaFuncAttributeMaxDynamicSharedMemorySize, SM_GEMM);
    cudaFuncSetAttribute(k_gemm_tc<64,  false, false>, cudaFuncAttributeMaxDynamicSharedMemorySize, SM_GEMM);

    // CSR build (by dst)
    cudaMemsetAsync(countsPtr, 0, N_NODES * sizeof(int));
    k_hist<<<(N_EDGES + 255) / 256, 256>>>(dst);
    int nb = (N_NODES + 1023) / 1024;   // 98
    k_scan1<<<nb, 1024>>>();
    k_scan2<<<1, 128>>>(nb);
    k_scan3<<<(N_NODES + 1 + 255) / 256, 256>>>();
    k_scatter<<<(N_EDGES + 255) / 256, 256>>>(src, dst);

    dim3 aggGrid((N_NODES + 7) / 8);            // 8 warps/block of 256 threads
    int gemmGrid = (N_NODES + 255) / 256;       // 391

    // layer 0: agg -> gemm(+b0, relu)
    k_agg<<<aggGrid, 256>>>(features, norm, bufA);
    k_gemm_tc<128, true, true><<<gemmGrid, 512, SM_GEMM>>>(bufA, W0, b0, bufB);
    // layer 1: agg -> gemm(+b1, relu)
    k_agg<<<aggGrid, 256>>>(bufB, norm, bufA);
    k_gemm_tc<128, true, true><<<gemmGrid, 512, SM_GEMM>>>(bufA, W1, b1, bufB);
    // layer 2 (linear, so reorder): Y = h @ W2 (128->64), then 64-wide agg
    // with norm scaling and bias fused: out = norm * segsum(Y[src]) + b2
    k_gemm_tc<64, false, false><<<gemmGrid, 512, SM_GEMM>>>(bufB, W2, nullptr, bufA);
    k_agg64_bias<<<aggGrid, 256>>>(bufA, norm, b2, out);
}

// round 7
// speedup vs baseline: 1.7345x; 1.0145x over previous
#include <cuda_runtime.h>
#include <cstdint>

#define N_NODES 100000
#define N_EDGES 1600000
#define F 128
#define NCLS 64

// ---------------- scratch (no allocation allowed; __device__ globals) ------
__device__ float g_bufA[(size_t)N_NODES * F];
__device__ float g_bufB[(size_t)N_NODES * F];
__device__ int   g_counts[N_NODES];
__device__ int   g_rowstart[N_NODES + 1];
__device__ int   g_cursor[N_NODES];
__device__ int   g_eidx[N_EDGES];
__device__ int   g_blocksums[128];

// ---------------- CSR build -----------------------------------------------
__global__ void k_hist(const int* __restrict__ dst) {
    int e = blockIdx.x * blockDim.x + threadIdx.x;
    if (e < N_EDGES) atomicAdd(&g_counts[dst[e]], 1);
}

__global__ void k_scan1() {
    __shared__ int s[1024];
    int t = threadIdx.x;
    int i = blockIdx.x * 1024 + t;
    int v = (i < N_NODES) ? g_counts[i] : 0;
    s[t] = v;
    __syncthreads();
    for (int off = 1; off < 1024; off <<= 1) {
        int x = (t >= off) ? s[t - off] : 0;
        __syncthreads();
        s[t] += x;
        __syncthreads();
    }
    if (i < N_NODES) g_rowstart[i] = s[t] - v;   // exclusive
    if (t == 1023) g_blocksums[blockIdx.x] = s[1023];
}

__global__ void k_scan2(int nblocks) {
    __shared__ int s[128];
    int t = threadIdx.x;
    int v = (t < nblocks) ? g_blocksums[t] : 0;
    s[t] = v;
    __syncthreads();
    for (int off = 1; off < 128; off <<= 1) {
        int x = (t >= off) ? s[t - off] : 0;
        __syncthreads();
        s[t] += x;
        __syncthreads();
    }
    if (t < nblocks) g_blocksums[t] = s[t] - v;  // exclusive
}

__global__ void k_scan3() {
    int i = blockIdx.x * blockDim.x + threadIdx.x;
    if (i < N_NODES) {
        int r = g_rowstart[i] + g_blocksums[i >> 10];
        g_rowstart[i] = r;
        g_cursor[i]   = r;
    }
    if (i == N_NODES) g_rowstart[N_NODES] = N_EDGES;
}

__global__ void k_scatter(const int* __restrict__ src, const int* __restrict__ dst) {
    int e = blockIdx.x * blockDim.x + threadIdx.x;
    if (e < N_EDGES) {
        int p = atomicAdd(&g_cursor[dst[e]], 1);
        g_eidx[p] = src[e];
    }
}

// ---------------- aggregation (128-wide) + norm + bias (+relu) ------------
// out[node] = maybe_relu(norm[node] * sum_{e in(node)} Y[src(e)] + bias)
template<bool RELU>
__global__ void k_agg_epi(const float* __restrict__ Y, const float* __restrict__ norm,
                          const float* __restrict__ bias, float* __restrict__ out) {
    int w = (blockIdx.x * blockDim.x + threadIdx.x) >> 5;
    int lane = threadIdx.x & 31;
    if (w >= N_NODES) return;
    int beg = g_rowstart[w];
    int end = g_rowstart[w + 1];

    float ax = 0.f, ay = 0.f, az = 0.f, aw = 0.f;
    int e = beg;
    for (; e + 4 <= end; e += 4) {
        int s0 = g_eidx[e + 0];
        int s1 = g_eidx[e + 1];
        int s2 = g_eidx[e + 2];
        int s3 = g_eidx[e + 3];
        float4 v0 = *(const float4*)(Y + (size_t)s0 * F + lane * 4);
        float4 v1 = *(const float4*)(Y + (size_t)s1 * F + lane * 4);
        float4 v2 = *(const float4*)(Y + (size_t)s2 * F + lane * 4);
        float4 v3 = *(const float4*)(Y + (size_t)s3 * F + lane * 4);
        ax += v0.x + v1.x + v2.x + v3.x;
        ay += v0.y + v1.y + v2.y + v3.y;
        az += v0.z + v1.z + v2.z + v3.z;
        aw += v0.w + v1.w + v2.w + v3.w;
    }
    for (; e < end; ++e) {
        int s = g_eidx[e];
        float4 v = *(const float4*)(Y + (size_t)s * F + lane * 4);
        ax += v.x; ay += v.y; az += v.z; aw += v.w;
    }
    float nf = norm[w];
    float4 b = *(const float4*)(bias + lane * 4);
    float4 r = make_float4(ax * nf + b.x, ay * nf + b.y,
                           az * nf + b.z, aw * nf + b.w);
    if (RELU) {
        r.x = fmaxf(r.x, 0.f); r.y = fmaxf(r.y, 0.f);
        r.z = fmaxf(r.z, 0.f); r.w = fmaxf(r.w, 0.f);
    }
    *(float4*)(out + (size_t)w * F + lane * 4) = r;
}

// ---------------- aggregation (64-wide) + norm + bias, final layer --------
__global__ void k_agg64_bias(const float* __restrict__ Y, const float* __restrict__ norm,
                             const float* __restrict__ bias, float* __restrict__ out) {
    int w = (blockIdx.x * blockDim.x + threadIdx.x) >> 5;
    int lane = threadIdx.x & 31;
    if (w >= N_NODES) return;
    int beg = g_rowstart[w];
    int end = g_rowstart[w + 1];

    float ax = 0.f, ay = 0.f;
    int e = beg;
    for (; e + 4 <= end; e += 4) {
        int s0 = g_eidx[e + 0];
        int s1 = g_eidx[e + 1];
        int s2 = g_eidx[e + 2];
        int s3 = g_eidx[e + 3];
        float2 v0 = *(const float2*)(Y + (size_t)s0 * NCLS + lane * 2);
        float2 v1 = *(const float2*)(Y + (size_t)s1 * NCLS + lane * 2);
        float2 v2 = *(const float2*)(Y + (size_t)s2 * NCLS + lane * 2);
        float2 v3 = *(const float2*)(Y + (size_t)s3 * NCLS + lane * 2);
        ax += v0.x + v1.x + v2.x + v3.x;
        ay += v0.y + v1.y + v2.y + v3.y;
    }
    for (; e < end; ++e) {
        int s = g_eidx[e];
        float2 v = *(const float2*)(Y + (size_t)s * NCLS + lane * 2);
        ax += v.x; ay += v.y;
    }
    float nf = norm[w];
    float2 b = *(const float2*)(bias + lane * 2);
    float2 r = make_float2(ax * nf + b.x, ay * nf + b.y);
    *(float2*)(out + (size_t)w * NCLS + lane * 2) = r;
}

// ---------------- tensor-core GEMM (tf32 mma.sync, fp32 accumulate) -------
// C[M, NOUT] = A[M,128] @ W[128,NOUT]   (no epilogue; moved into agg)
__device__ __forceinline__ uint32_t f2tf32(float f) {
    uint32_t u;
    asm("cvt.rna.tf32.f32 %0, %1;" : "=r"(u) : "f"(f));
    return u;
}

__device__ __forceinline__ void mma_tf32(float c[4],
                                         uint32_t a0, uint32_t a1, uint32_t a2, uint32_t a3,
                                         uint32_t b0, uint32_t b1) {
    asm volatile(
        "mma.sync.aligned.m16n8k8.row.col.f32.tf32.tf32.f32 "
        "{%0,%1,%2,%3}, {%4,%5,%6,%7}, {%8,%9}, {%0,%1,%2,%3};\n"
        : "+f"(c[0]), "+f"(c[1]), "+f"(c[2]), "+f"(c[3])
        : "r"(a0), "r"(a1), "r"(a2), "r"(a3), "r"(b0), "r"(b1));
}

template<int NOUT>
__global__ void __launch_bounds__(512, 1)
k_gemm_tc(const float* __restrict__ A, const float* __restrict__ W,
          float* __restrict__ C) {
    constexpr int BM  = 256;
    constexpr int AST = 132;            // conflict-free A stride (words)
    constexpr int WST = 136;            // conflict-free W stride (words)
    constexpr int NTILES = NOUT / 32;

    extern __shared__ uint32_t sm[];
    uint32_t* As = sm;                  // [BM][AST] tf32 bits
    uint32_t* Ws = sm + BM * AST;       // [128][WST] tf32 bits

    int tid = threadIdx.x;
    int m0 = blockIdx.x * BM;

    for (int idx = tid * 4; idx < 128 * NOUT; idx += 512 * 4) {
        int k = idx / NOUT, n = idx % NOUT;
        float4 v = *(const float4*)&W[idx];
        uint32_t* p = &Ws[k * WST + n];
        p[0] = f2tf32(v.x); p[1] = f2tf32(v.y);
        p[2] = f2tf32(v.z); p[3] = f2tf32(v.w);
    }

    for (int idx = tid; idx < BM * 32; idx += 512) {
        int m = idx >> 5, kq = idx & 31;
        float4 v = make_float4(0.f, 0.f, 0.f, 0.f);
        if (m0 + m < N_NODES)
            v = *(const float4*)&A[(size_t)(m0 + m) * 128 + kq * 4];
        uint32_t* p = &As[m * AST + kq * 4];
        p[0] = f2tf32(v.x); p[1] = f2tf32(v.y);
        p[2] = f2tf32(v.z); p[3] = f2tf32(v.w);
    }
    __syncthreads();

    int wid  = tid >> 5, lane = tid & 31;
    int wm   = wid & 3;
    int wn   = wid >> 2;
    int mbase = wm * 64;
    int nbase = wn * (NOUT / 4);
    int r = lane >> 2;
    int c = lane & 3;

    float acc[4][NTILES][4];
#pragma unroll
    for (int mt = 0; mt < 4; ++mt)
#pragma unroll
        for (int nt = 0; nt < NTILES; ++nt)
#pragma unroll
            for (int i = 0; i < 4; ++i) acc[mt][nt][i] = 0.f;

#pragma unroll 2
    for (int k0 = 0; k0 < 128; k0 += 8) {
        uint32_t af[4][4];
#pragma unroll
        for (int mt = 0; mt < 4; ++mt) {
            int row = mbase + mt * 16 + r;
            af[mt][0] = As[row * AST + k0 + c];
            af[mt][1] = As[(row + 8) * AST + k0 + c];
            af[mt][2] = As[row * AST + k0 + c + 4];
            af[mt][3] = As[(row + 8) * AST + k0 + c + 4];
        }
        uint32_t bf[NTILES][2];
#pragma unroll
        for (int nt = 0; nt < NTILES; ++nt) {
            int col = nbase + nt * 8 + r;
            bf[nt][0] = Ws[(k0 + c) * WST + col];
            bf[nt][1] = Ws[(k0 + c + 4) * WST + col];
        }
#pragma unroll
        for (int mt = 0; mt < 4; ++mt)
#pragma unroll
            for (int nt = 0; nt < NTILES; ++nt)
                mma_tf32(acc[mt][nt], af[mt][0], af[mt][1], af[mt][2], af[mt][3],
                         bf[nt][0], bf[nt][1]);
    }

#pragma unroll
    for (int nt = 0; nt < NTILES; ++nt) {
        int col = nbase + nt * 8 + 2 * c;
#pragma unroll
        for (int mt = 0; mt < 4; ++mt) {
            int row = m0 + mbase + mt * 16 + r;
            if (row < N_NODES)
                *(float2*)&C[(size_t)row * NOUT + col] =
                    make_float2(acc[mt][nt][0], acc[mt][nt][1]);
            if (row + 8 < N_NODES)
                *(float2*)&C[(size_t)(row + 8) * NOUT + col] =
                    make_float2(acc[mt][nt][2], acc[mt][nt][3]);
        }
    }
}

// ---------------- launch ---------------------------------------------------
extern "C" void kernel_launch(void* const* d_in, const int* in_sizes, int n_in,
                              void* d_out, int out_size) {
    const float* features = (const float*)d_in[0];
    const float* norm     = (const float*)d_in[1];
    const float* W0       = (const float*)d_in[2];
    const float* b0       = (const float*)d_in[3];
    const float* W1       = (const float*)d_in[4];
    const float* b1       = (const float*)d_in[5];
    const float* W2       = (const float*)d_in[6];
    const float* b2       = (const float*)d_in[7];
    const int*   src      = (const int*)d_in[8];
    const int*   dst      = (const int*)d_in[9];
    float* out = (float*)d_out;

    float *bufA = nullptr, *bufB = nullptr;
    int* countsPtr = nullptr;
    cudaGetSymbolAddress((void**)&bufA, g_bufA);
    cudaGetSymbolAddress((void**)&bufB, g_bufB);
    cudaGetSymbolAddress((void**)&countsPtr, g_counts);

    const int SM_GEMM = (256 * 132 + 128 * 136) * 4;   // 204800 B
    cudaFuncSetAttribute(k_gemm_tc<128>, cudaFuncAttributeMaxDynamicSharedMemorySize, SM_GEMM);
    cudaFuncSetAttribute(k_gemm_tc<64>,  cudaFuncAttributeMaxDynamicSharedMemorySize, SM_GEMM);

    // One-time side-stream + events for the CSR ∥ gemm0 fork (resource init
    // only; the launched work is identical on every call).
    static cudaStream_t s2 = nullptr;
    static cudaEvent_t evFork = nullptr, evJoin = nullptr;
    if (!s2) {
        cudaStreamCreateWithFlags(&s2, cudaStreamNonBlocking);
        cudaEventCreateWithFlags(&evFork, cudaEventDisableTiming);
        cudaEventCreateWithFlags(&evJoin, cudaEventDisableTiming);
    }

    dim3 aggGrid((N_NODES + 7) / 8);            // warp per node
    int gemmGrid = (N_NODES + 255) / 256;       // 391

    // ---- fork: gemm0 (Y0 = feat @ W0, no deps on CSR) on s2 ----
    cudaEventRecord(evFork, 0);
    cudaStreamWaitEvent(s2, evFork, 0);
    k_gemm_tc<128><<<gemmGrid, 512, SM_GEMM, s2>>>(features, W0, bufA);
    cudaEventRecord(evJoin, s2);

    // ---- CSR build (by dst) on main stream, concurrent with gemm0 ----
    cudaMemsetAsync(countsPtr, 0, N_NODES * sizeof(int));
    k_hist<<<(N_EDGES + 255) / 256, 256>>>(dst);
    int nb = (N_NODES + 1023) / 1024;   // 98
    k_scan1<<<nb, 1024>>>();
    k_scan2<<<1, 128>>>(nb);
    k_scan3<<<(N_NODES + 1 + 255) / 256, 256>>>();
    k_scatter<<<(N_EDGES + 255) / 256, 256>>>(src, dst);

    // ---- join ----
    cudaStreamWaitEvent(0, evJoin, 0);

    // layer 0 epilogue: h1 = relu(norm * segsum(Y0[src]) + b0)
    k_agg_epi<true><<<aggGrid, 256>>>(bufA, norm, b0, bufB);
    // layer 1: Y1 = h1 @ W1 ; h2 = relu(norm * segsum(Y1[src]) + b1)
    k_gemm_tc<128><<<gemmGrid, 512, SM_GEMM>>>(bufB, W1, bufA);
    k_agg_epi<true><<<aggGrid, 256>>>(bufA, norm, b1, bufB);
    // layer 2: Y2 = h2 @ W2 (64-wide) ; out = norm * segsum(Y2[src]) + b2
    k_gemm_tc<64><<<gemmGrid, 512, SM_GEMM>>>(bufB, W2, bufA);
    k_agg64_bias<<<aggGrid, 256>>>(bufA, norm, b2, out);
}